// round 6
// baseline (speedup 1.0000x reference)
#include <cuda_runtime.h>
#include <cuda_bf16.h>
#include <cstdint>

#define Nn 50000
#define Ee 400000
#define F_IN 128
#define HIDc 64
#define Hh 4
#define Dd 16
#define Cc 16

// ---------------- device scratch (static, no allocation) ----------------
__device__ int   g_is64;
__device__ int   g_src[Ee];
__device__ int   g_dst[Ee];
__device__ int   g_indeg[Nn];
__device__ int   g_rowstart[Nn + 1];
__device__ int   g_cursor[Nn];
__device__ int   g_csr[Ee];
__device__ float g_Q[Nn * 64];
__device__ float g_K0[Nn * 64];
__device__ float g_V[Nn * 64];
__device__ float g_Ka[Nn * 64];
__device__ float g_Kb[Nn * 64];
__device__ float g_Ma[(size_t)Nn * 1024];
__device__ float g_Mb[(size_t)Nn * 1024];
__device__ float g_hid[Nn * 64];
__device__ float g_gamma[16];   // [h][k], k=0 unused
__device__ float g_temp0[4];

// ---------------- small setup kernels ----------------
__global__ void k_zero_indeg() {
    int i = blockIdx.x * blockDim.x + threadIdx.x;
    if (i < Nn) g_indeg[i] = 0;
}

// Detect whether edge_index buffer is int64 or int32.
// If int64 (node ids < 2^31), every odd int32 word of the first 2048 is zero.
__global__ void k_sniff(const int* __restrict__ p) {
    if (threadIdx.x == 0 && blockIdx.x == 0) {
        int nz = 0;
        for (int i = 1; i < 2048; i += 2) nz += (p[i] != 0);
        g_is64 = (nz == 0) ? 1 : 0;
    }
}

__global__ void k_edges(const void* __restrict__ ei) {
    int e = blockIdx.x * blockDim.x + threadIdx.x;
    if (e >= Ee) return;
    int s, d;
    if (g_is64) {
        const long long* p = (const long long*)ei;
        s = (int)p[e]; d = (int)p[Ee + e];
    } else {
        const int* p = (const int*)ei;
        s = p[e]; d = p[Ee + e];
    }
    g_src[e] = s;
    g_dst[e] = d;
    atomicAdd(&g_indeg[d], 1);
}

// single-block exclusive scan of indeg -> rowstart (chunked, one pass)
__global__ void k_scan() {
    __shared__ int sh[1024];
    int tid = threadIdx.x;
    const int CH = (Nn + 1023) / 1024;  // 49
    int base = tid * CH;
    int sum = 0;
    for (int i = 0; i < CH; i++) {
        int idx = base + i;
        if (idx < Nn) sum += g_indeg[idx];
    }
    sh[tid] = sum;
    __syncthreads();
    for (int off = 1; off < 1024; off <<= 1) {
        int t = (tid >= off) ? sh[tid - off] : 0;
        __syncthreads();
        sh[tid] += t;
        __syncthreads();
    }
    int run = sh[tid] - sum;  // exclusive prefix for this chunk
    for (int i = 0; i < CH; i++) {
        int idx = base + i;
        if (idx < Nn) {
            g_rowstart[idx] = run;
            run += g_indeg[idx];
        }
    }
    if (tid == 1023) g_rowstart[Nn] = sh[1023];
}

__global__ void k_cursor() {
    int i = blockIdx.x * blockDim.x + threadIdx.x;
    if (i < Nn) g_cursor[i] = g_rowstart[i];
}

__global__ void k_scatter() {
    int e = blockIdx.x * blockDim.x + threadIdx.x;
    if (e >= Ee) return;
    int d = g_dst[e];
    int pos = atomicAdd(&g_cursor[d], 1);
    g_csr[pos] = g_src[e];
}

// sort each CSR row ascending -> deterministic summation order
__global__ void k_sortrows() {
    int n = blockIdx.x * blockDim.x + threadIdx.x;
    if (n >= Nn) return;
    int beg = g_rowstart[n], end = g_rowstart[n + 1];
    for (int i = beg + 1; i < end; i++) {
        int v = g_csr[i];
        int j = i - 1;
        while (j >= beg && g_csr[j] > v) { g_csr[j + 1] = g_csr[j]; j--; }
        g_csr[j + 1] = v;
    }
}

__global__ void k_gamma(const float* __restrict__ hopwise, const float* __restrict__ temp) {
    if (threadIdx.x == 0 && blockIdx.x == 0) {
        for (int k = 0; k < 4; k++) {
            float mx = -1e30f;
            for (int h = 0; h < 4; h++) mx = fmaxf(mx, temp[h * 4 + k]);
            float ex[4], ssum = 0.f;
            for (int h = 0; h < 4; h++) { ex[h] = __expf(temp[h * 4 + k] - mx); ssum += ex[h]; }
            for (int h = 0; h < 4; h++) g_gamma[h * 4 + k] = hopwise[k] * ex[h] / ssum;
        }
        for (int h = 0; h < 4; h++) g_temp0[h] = temp[h * 4 + 0];
    }
}

// ---------------- fused input transform + QKV ----------------
// h = relu(x@Wi+bi); Q=1+elu(h@Wq+bq); K=1+elu(h@Wk+bk); V=h@Wv+bv
__global__ __launch_bounds__(256) void k_qkv(
    const float* __restrict__ x,
    const float* __restrict__ Wi, const float* __restrict__ bi,
    const float* __restrict__ Wq, const float* __restrict__ bq,
    const float* __restrict__ Wk, const float* __restrict__ bk,
    const float* __restrict__ Wv, const float* __restrict__ bv)
{
    __shared__ float hs[4][64];
    int j = threadIdx.x & 63;
    int g = threadIdx.x >> 6;          // 4 node slots per iteration
    int n0 = blockIdx.x * 64;
    for (int it = 0; it < 16; ++it) {
        int n = n0 + it * 4 + g;
        float acc = __ldg(bi + j);
        if (n < Nn) {
            const float* xr = x + (size_t)n * F_IN;
            #pragma unroll 8
            for (int k2 = 0; k2 < F_IN; k2++)
                acc = fmaf(__ldg(xr + k2), __ldg(Wi + k2 * 64 + j), acc);
        }
        __syncthreads();
        hs[g][j] = fmaxf(acc, 0.f);
        __syncthreads();
        if (n < Nn) {
            float aq = __ldg(bq + j), ak = __ldg(bk + j), av = __ldg(bv + j);
            #pragma unroll
            for (int k2 = 0; k2 < 64; k2++) {
                float hv = hs[g][k2];
                aq = fmaf(hv, __ldg(Wq + k2 * 64 + j), aq);
                ak = fmaf(hv, __ldg(Wk + k2 * 64 + j), ak);
                av = fmaf(hv, __ldg(Wv + k2 * 64 + j), av);
            }
            g_Q[n * 64 + j]  = (aq > 0.f) ? (1.f + aq) : __expf(aq);
            g_K0[n * 64 + j] = (ak > 0.f) ? (1.f + ak) : __expf(ak);
            g_V[n * 64 + j]  = av;
        }
    }
}

// ---------------- hop epilogue (shared by all hop kernels) ----------------
// lane = d*2 + ch; lane owns M[d][ch*8 .. ch*8+7] (contiguous 32B of the 1KB block)
__device__ __forceinline__ void hop_epilogue(
    int n, int h, int lane, int d, int ch,
    const float m[8], float kt, int hop, bool first, bool writeM,
    float* __restrict__ Mout, float* __restrict__ Kout)
{
    float q = g_Q[n * 64 + h * 16 + d];
    float den = q * kt;
    #pragma unroll
    for (int msk = 2; msk <= 16; msk <<= 1) den += __shfl_xor_sync(0xffffffffu, den, msk);
    den += 1e-5f;

    float hm[8];
    #pragma unroll
    for (int jj = 0; jj < 8; jj++) {
        float t = q * m[jj];
        #pragma unroll
        for (int msk = 2; msk <= 16; msk <<= 1) t += __shfl_xor_sync(0xffffffffu, t, msk);
        hm[jj] = t;
    }

    if (writeM) {
        float4* mo = (float4*)(Mout + (size_t)n * 1024 + h * 256 + lane * 8);
        mo[0] = make_float4(m[0], m[1], m[2], m[3]);
        mo[1] = make_float4(m[4], m[5], m[6], m[7]);
        if (ch == 0) Kout[n * 64 + h * 16 + d] = kt;
    }

    if (d == 0) {  // lanes 0 (c=0..7) and 1 (c=8..15) write hidden
        float inv = g_gamma[h * 4 + hop] / den;
        float* hp = g_hid + n * 64 + h * 16 + ch * 8;
        if (first) {
            float t0 = g_temp0[h];
            const float* vp = g_V + n * 64 + h * 16 + ch * 8;
            #pragma unroll
            for (int jj = 0; jj < 8; jj++) hp[jj] = vp[jj] * t0 + hm[jj] * inv;
        } else {
            #pragma unroll
            for (int jj = 0; jj < 8; jj++) hp[jj] += hm[jj] * inv;
        }
    }
}

// ---------------- hop 1: form M0 = Kt0 (x) V on the fly ----------------
__global__ __launch_bounds__(256) void k_hop1() {
    int w = (blockIdx.x * blockDim.x + threadIdx.x) >> 5;
    int lane = threadIdx.x & 31;
    if (w >= Nn * Hh) return;
    int n = w >> 2, h = w & 3;
    int d = lane >> 1, ch = lane & 1;

    float m[8] = {0, 0, 0, 0, 0, 0, 0, 0};
    float kt = 0.f;
    int beg = g_rowstart[n], end = g_rowstart[n + 1];
    #pragma unroll 2
    for (int e = beg; e < end; ++e) {
        int s = g_csr[e];
        float ks = __ldg(g_K0 + s * 64 + h * 16 + d);
        const float4* vb = (const float4*)(g_V + s * 64 + h * 16 + ch * 8);
        float4 va = __ldg(vb), vc = __ldg(vb + 1);
        kt += ks;
        m[0] = fmaf(ks, va.x, m[0]); m[1] = fmaf(ks, va.y, m[1]);
        m[2] = fmaf(ks, va.z, m[2]); m[3] = fmaf(ks, va.w, m[3]);
        m[4] = fmaf(ks, vc.x, m[4]); m[5] = fmaf(ks, vc.y, m[5]);
        m[6] = fmaf(ks, vc.z, m[6]); m[7] = fmaf(ks, vc.w, m[7]);
    }
    hop_epilogue(n, h, lane, d, ch, m, kt, /*hop=*/1, /*first=*/true, /*writeM=*/true,
                 g_Ma, g_Ka);
}

// ---------------- hops 2,3: gather dense M ----------------
__global__ __launch_bounds__(256) void k_hop23(int hop) {
    int w = (blockIdx.x * blockDim.x + threadIdx.x) >> 5;
    int lane = threadIdx.x & 31;
    if (w >= Nn * Hh) return;
    int n = w >> 2, h = w & 3;
    int d = lane >> 1, ch = lane & 1;

    const float* __restrict__ Min  = (hop == 2) ? g_Ma : g_Mb;
    const float* __restrict__ Kin  = (hop == 2) ? g_Ka : g_Kb;
    float*       Mout = g_Mb;
    float*       Kout = g_Kb;
    bool writeM = (hop == 2);

    float m[8] = {0, 0, 0, 0, 0, 0, 0, 0};
    float kt = 0.f;
    int beg = g_rowstart[n], end = g_rowstart[n + 1];
    #pragma unroll 2
    for (int e = beg; e < end; ++e) {
        int s = g_csr[e];
        const float4* mb = (const float4*)(Min + (size_t)s * 1024 + h * 256 + lane * 8);
        float4 a = __ldg(mb), b = __ldg(mb + 1);
        m[0] += a.x; m[1] += a.y; m[2] += a.z; m[3] += a.w;
        m[4] += b.x; m[5] += b.y; m[6] += b.z; m[7] += b.w;
        kt += __ldg(Kin + s * 64 + h * 16 + d);
    }
    hop_epilogue(n, h, lane, d, ch, m, kt, hop, /*first=*/false, writeM,
                 Mout, Kout);
}

// ---------------- output projection ----------------
__global__ __launch_bounds__(256) void k_out(const float* __restrict__ Wo,
                                             const float* __restrict__ bo,
                                             float* __restrict__ out)
{
    int t = blockIdx.x * blockDim.x + threadIdx.x;
    int n = t >> 4, c = t & 15;
    if (n >= Nn) return;
    float acc = __ldg(bo + c);
    const float* hr = g_hid + n * 64;
    #pragma unroll
    for (int k = 0; k < 64; k++)
        acc = fmaf(hr[k], __ldg(Wo + k * 16 + c), acc);
    out[n * 16 + c] = acc;
}

// ---------------- launcher ----------------
extern "C" void kernel_launch(void* const* d_in, const int* in_sizes, int n_in,
                              void* d_out, int out_size)
{
    const float* x       = (const float*)d_in[0];
    const void*  ei      = d_in[1];
    const float* Wi      = (const float*)d_in[2];
    const float* bi      = (const float*)d_in[3];
    const float* Wq      = (const float*)d_in[4];
    const float* bq      = (const float*)d_in[5];
    const float* Wk      = (const float*)d_in[6];
    const float* bk      = (const float*)d_in[7];
    const float* Wv      = (const float*)d_in[8];
    const float* bv      = (const float*)d_in[9];
    const float* Wo      = (const float*)d_in[10];
    const float* bo      = (const float*)d_in[11];
    const float* hopwise = (const float*)d_in[12];
    const float* temp    = (const float*)d_in[13];
    float* out = (float*)d_out;

    k_zero_indeg<<<(Nn + 255) / 256, 256>>>();
    k_sniff<<<1, 32>>>((const int*)ei);
    k_edges<<<(Ee + 255) / 256, 256>>>(ei);
    k_scan<<<1, 1024>>>();
    k_cursor<<<(Nn + 255) / 256, 256>>>();
    k_scatter<<<(Ee + 255) / 256, 256>>>();
    k_sortrows<<<(Nn + 255) / 256, 256>>>();
    k_gamma<<<1, 32>>>(hopwise, temp);
    k_qkv<<<(Nn + 63) / 64, 256>>>(x, Wi, bi, Wq, bq, Wk, bk, Wv, bv);

    int hop_blocks = (Nn * Hh + 7) / 8;  // 8 warps per block, 1 warp per (node,head)
    k_hop1<<<hop_blocks, 256>>>();
    k_hop23<<<hop_blocks, 256>>>(2);
    k_hop23<<<hop_blocks, 256>>>(3);

    k_out<<<(Nn * 16 + 255) / 256, 256>>>(Wo, bo, out);
}

// round 8
// speedup vs baseline: 1.1437x; 1.1437x over previous
#include <cuda_runtime.h>
#include <cuda_bf16.h>
#include <cstdint>

#define Nn 50000
#define Ee 400000
#define F_IN 128
#define Hh 4
#define FULLMASK 0xffffffffu
#define NB 196   // ceil(Nn/256)

// ---------------- device scratch (static, no allocation) ----------------
__device__ int   g_is64;
__device__ int   g_src[Ee];
__device__ int   g_dst[Ee];
__device__ int   g_indeg[Nn];
__device__ int   g_rowstart[Nn + 1];
__device__ int   g_cursor[Nn];
__device__ int   g_csr[Ee];
__device__ int   g_blocksum[256];
__device__ int   g_blockoff[256];
// head-major: [h][n][16]
__device__ float g_Q[Hh * Nn * 16];
__device__ float g_K0[Hh * Nn * 16];
__device__ float g_V[Hh * Nn * 16];
__device__ float g_Ka[Hh * Nn * 16];
__device__ float g_Kb[Hh * Nn * 16];
// head-major: [h][n][256]   (d*16+c inside)
__device__ float g_Ma[(size_t)Hh * Nn * 256];
__device__ float g_Mb[(size_t)Hh * Nn * 256];
__device__ float g_hid[Nn * 64];        // node-major for k_out
__device__ float g_gamma[16];           // [h][k], k=0 unused
__device__ float g_temp0[4];

// ---------------- setup kernels ----------------
__global__ void k_zero_indeg() {
    int i = blockIdx.x * blockDim.x + threadIdx.x;
    if (i < Nn) g_indeg[i] = 0;
}

// int64 vs int32 sniff: if int64 (ids < 2^31), every odd int32 word is zero.
__global__ void k_sniff(const int* __restrict__ p) {
    int lane = threadIdx.x;
    int nz = 0;
    #pragma unroll
    for (int k = 0; k < 32; k++) {
        int i = 1 + 2 * (lane + 32 * k);
        nz += (p[i] != 0);
    }
    #pragma unroll
    for (int o = 16; o; o >>= 1) nz += __shfl_down_sync(FULLMASK, nz, o);
    if (lane == 0) g_is64 = (nz == 0) ? 1 : 0;
}

__global__ void k_edges(const void* __restrict__ ei) {
    int e = blockIdx.x * blockDim.x + threadIdx.x;
    if (e >= Ee) return;
    int s, d;
    if (g_is64) {
        const long long* p = (const long long*)ei;
        s = (int)p[e]; d = (int)p[Ee + e];
    } else {
        const int* p = (const int*)ei;
        s = p[e]; d = p[Ee + e];
    }
    g_src[e] = s;
    g_dst[e] = d;
    atomicAdd(&g_indeg[d], 1);
}

// grid scan, stage A: per-block sums
__global__ __launch_bounds__(256) void k_scanA() {
    __shared__ int sh[8];
    int i = blockIdx.x * 256 + threadIdx.x;
    int v = (i < Nn) ? g_indeg[i] : 0;
    #pragma unroll
    for (int o = 16; o; o >>= 1) v += __shfl_down_sync(FULLMASK, v, o);
    if ((threadIdx.x & 31) == 0) sh[threadIdx.x >> 5] = v;
    __syncthreads();
    if (threadIdx.x < 8) {
        int t = sh[threadIdx.x];
        #pragma unroll
        for (int o = 4; o; o >>= 1) t += __shfl_down_sync(0xffu, t, o);
        if (threadIdx.x == 0) g_blocksum[blockIdx.x] = t;
    }
}

// stage B: scan the block sums (1 block)
__global__ __launch_bounds__(256) void k_scanB() {
    __shared__ int sh[256];
    int tid = threadIdx.x;
    int v = (tid < NB) ? g_blocksum[tid] : 0;
    sh[tid] = v;
    __syncthreads();
    for (int o = 1; o < 256; o <<= 1) {
        int t = (tid >= o) ? sh[tid - o] : 0;
        __syncthreads();
        sh[tid] += t;
        __syncthreads();
    }
    if (tid < NB) g_blockoff[tid] = sh[tid] - v;
}

// stage C: local exclusive scan + block offset; write rowstart AND cursor
__global__ __launch_bounds__(256) void k_scanC() {
    __shared__ int sh[256];
    int tid = threadIdx.x;
    int i = blockIdx.x * 256 + tid;
    int v = (i < Nn) ? g_indeg[i] : 0;
    sh[tid] = v;
    __syncthreads();
    for (int o = 1; o < 256; o <<= 1) {
        int t = (tid >= o) ? sh[tid - o] : 0;
        __syncthreads();
        sh[tid] += t;
        __syncthreads();
    }
    int excl = sh[tid] - v + g_blockoff[blockIdx.x];
    if (i < Nn) { g_rowstart[i] = excl; g_cursor[i] = excl; }
    if (i == 0) g_rowstart[Nn] = Ee;
}

__global__ void k_scatter() {
    int e = blockIdx.x * blockDim.x + threadIdx.x;
    if (e >= Ee) return;
    int d = g_dst[e];
    int pos = atomicAdd(&g_cursor[d], 1);
    g_csr[pos] = g_src[e];
}

// sort each CSR row ascending -> deterministic summation order
__global__ void k_sortrows() {
    int n = blockIdx.x * blockDim.x + threadIdx.x;
    if (n >= Nn) return;
    int beg = g_rowstart[n], end = g_rowstart[n + 1];
    for (int i = beg + 1; i < end; i++) {
        int v = g_csr[i];
        int j = i - 1;
        while (j >= beg && g_csr[j] > v) { g_csr[j + 1] = g_csr[j]; j--; }
        g_csr[j + 1] = v;
    }
}

__global__ void k_gamma(const float* __restrict__ hopwise, const float* __restrict__ temp) {
    if (threadIdx.x == 0 && blockIdx.x == 0) {
        for (int k = 0; k < 4; k++) {
            float mx = -1e30f;
            for (int h = 0; h < 4; h++) mx = fmaxf(mx, temp[h * 4 + k]);
            float ex[4], ssum = 0.f;
            for (int h = 0; h < 4; h++) { ex[h] = __expf(temp[h * 4 + k] - mx); ssum += ex[h]; }
            for (int h = 0; h < 4; h++) g_gamma[h * 4 + k] = hopwise[k] * ex[h] / ssum;
        }
        for (int h = 0; h < 4; h++) g_temp0[h] = temp[h * 4 + 0];
    }
}

// ---------------- fused input transform + QKV ----------------
__global__ __launch_bounds__(256) void k_qkv(
    const float* __restrict__ x,
    const float* __restrict__ Wi, const float* __restrict__ bi,
    const float* __restrict__ Wq, const float* __restrict__ bq,
    const float* __restrict__ Wk, const float* __restrict__ bk,
    const float* __restrict__ Wv, const float* __restrict__ bv)
{
    __shared__ float hs[4][64];
    int j = threadIdx.x & 63;
    int g = threadIdx.x >> 6;          // 4 node slots per iteration
    int jh = j >> 4;                   // head of this output column
    int jd = j & 15;
    int n0 = blockIdx.x * 64;
    for (int it = 0; it < 16; ++it) {
        int n = n0 + it * 4 + g;
        float acc = __ldg(bi + j);
        if (n < Nn) {
            const float* xr = x + (size_t)n * F_IN;
            #pragma unroll 8
            for (int k2 = 0; k2 < F_IN; k2++)
                acc = fmaf(__ldg(xr + k2), __ldg(Wi + k2 * 64 + j), acc);
        }
        __syncthreads();
        hs[g][j] = fmaxf(acc, 0.f);
        __syncthreads();
        if (n < Nn) {
            float aq = __ldg(bq + j), ak = __ldg(bk + j), av = __ldg(bv + j);
            #pragma unroll
            for (int k2 = 0; k2 < 64; k2++) {
                float hv = hs[g][k2];
                aq = fmaf(hv, __ldg(Wq + k2 * 64 + j), aq);
                ak = fmaf(hv, __ldg(Wk + k2 * 64 + j), ak);
                av = fmaf(hv, __ldg(Wv + k2 * 64 + j), av);
            }
            size_t hm = (size_t)jh * Nn * 16 + n * 16 + jd;   // head-major
            g_Q[hm]  = (aq > 0.f) ? (1.f + aq) : __expf(aq);
            g_K0[hm] = (ak > 0.f) ? (1.f + ak) : __expf(ak);
            g_V[hm]  = av;
        }
    }
}

// ---------------- hop epilogue (head-major inputs) ----------------
// lane = d*2 + ch; lane owns M[d][ch*8 .. ch*8+7]
__device__ __forceinline__ void hop_epilogue(
    int n, int h, int lane, int d, int ch,
    const float m[8], float kt, int hop, bool first, bool writeM,
    float* __restrict__ Mout_h, float* __restrict__ Kout_h)
{
    float q = __ldg(g_Q + (size_t)h * Nn * 16 + n * 16 + d);
    float den = q * kt;
    #pragma unroll
    for (int msk = 2; msk <= 16; msk <<= 1) den += __shfl_xor_sync(FULLMASK, den, msk);
    den += 1e-5f;

    float hm[8];
    #pragma unroll
    for (int jj = 0; jj < 8; jj++) {
        float t = q * m[jj];
        #pragma unroll
        for (int msk = 2; msk <= 16; msk <<= 1) t += __shfl_xor_sync(FULLMASK, t, msk);
        hm[jj] = t;
    }

    if (writeM) {
        float4* mo = (float4*)(Mout_h + (size_t)n * 256 + lane * 8);
        mo[0] = make_float4(m[0], m[1], m[2], m[3]);
        mo[1] = make_float4(m[4], m[5], m[6], m[7]);
        if (ch == 0) Kout_h[n * 16 + d] = kt;
    }

    if (d == 0) {  // lanes 0 (c=0..7) and 1 (c=8..15) write hidden
        float inv = g_gamma[h * 4 + hop] / den;
        float* hp = g_hid + n * 64 + h * 16 + ch * 8;
        if (first) {
            float t0 = g_temp0[h];
            const float* vp = g_V + (size_t)h * Nn * 16 + n * 16 + ch * 8;
            #pragma unroll
            for (int jj = 0; jj < 8; jj++) hp[jj] = vp[jj] * t0 + hm[jj] * inv;
        } else {
            #pragma unroll
            for (int jj = 0; jj < 8; jj++) hp[jj] += hm[jj] * inv;
        }
    }
}

// ---------------- hop 1: form M0 = Kt0 (x) V on the fly ----------------
// w = h*Nn + n  -> blocks execute in head order -> per-head L2 residency
__global__ __launch_bounds__(256) void k_hop1() {
    int w = (blockIdx.x * 256 + threadIdx.x) >> 5;
    int lane = threadIdx.x & 31;
    if (w >= Nn * Hh) return;
    int h = w / Nn, n = w - h * Nn;
    int d = lane >> 1, ch = lane & 1;
    const float* __restrict__ K0h = g_K0 + (size_t)h * Nn * 16;
    const float* __restrict__ Vh  = g_V  + (size_t)h * Nn * 16;

    float m[8] = {0, 0, 0, 0, 0, 0, 0, 0};
    float kt = 0.f;
    int beg = g_rowstart[n];
    int deg = g_rowstart[n + 1] - beg;
    for (int base = 0; base < deg; base += 32) {
        int idx = base + lane;
        int s_l = (idx < deg) ? g_csr[beg + idx] : 0;
        int cnt = min(32, deg - base);
        #pragma unroll 4
        for (int i = 0; i < cnt; i++) {
            int s = __shfl_sync(FULLMASK, s_l, i);
            float ks = __ldg(K0h + s * 16 + d);
            const float4* vb = (const float4*)(Vh + s * 16 + ch * 8);
            float4 va = __ldg(vb), vc = __ldg(vb + 1);
            kt += ks;
            m[0] = fmaf(ks, va.x, m[0]); m[1] = fmaf(ks, va.y, m[1]);
            m[2] = fmaf(ks, va.z, m[2]); m[3] = fmaf(ks, va.w, m[3]);
            m[4] = fmaf(ks, vc.x, m[4]); m[5] = fmaf(ks, vc.y, m[5]);
            m[6] = fmaf(ks, vc.z, m[6]); m[7] = fmaf(ks, vc.w, m[7]);
        }
    }
    hop_epilogue(n, h, lane, d, ch, m, kt, 1, true, true,
                 g_Ma + (size_t)h * Nn * 256, g_Ka + (size_t)h * Nn * 16);
}

// ---------------- hops 2,3: gather dense M (head-major) ----------------
__global__ __launch_bounds__(256) void k_hop23(int hop) {
    int w = (blockIdx.x * 256 + threadIdx.x) >> 5;
    int lane = threadIdx.x & 31;
    if (w >= Nn * Hh) return;
    int h = w / Nn, n = w - h * Nn;
    int d = lane >> 1, ch = lane & 1;

    const float* __restrict__ Min_h = ((hop == 2) ? g_Ma : g_Mb) + (size_t)h * Nn * 256;
    const float* __restrict__ Kin_h = ((hop == 2) ? g_Ka : g_Kb) + (size_t)h * Nn * 16;
    bool writeM = (hop == 2);

    float m[8] = {0, 0, 0, 0, 0, 0, 0, 0};
    float kt = 0.f;
    int beg = g_rowstart[n];
    int deg = g_rowstart[n + 1] - beg;
    for (int base = 0; base < deg; base += 32) {
        int idx = base + lane;
        int s_l = (idx < deg) ? g_csr[beg + idx] : 0;
        int cnt = min(32, deg - base);
        #pragma unroll 4
        for (int i = 0; i < cnt; i++) {
            int s = __shfl_sync(FULLMASK, s_l, i);
            const float4* mb = (const float4*)(Min_h + (size_t)s * 256 + lane * 8);
            float4 a = __ldg(mb), b = __ldg(mb + 1);
            m[0] += a.x; m[1] += a.y; m[2] += a.z; m[3] += a.w;
            m[4] += b.x; m[5] += b.y; m[6] += b.z; m[7] += b.w;
            kt += __ldg(Kin_h + s * 16 + d);
        }
    }
    hop_epilogue(n, h, lane, d, ch, m, kt, hop, false, writeM,
                 g_Mb + (size_t)h * Nn * 256, g_Kb + (size_t)h * Nn * 16);
}

// ---------------- output projection ----------------
__global__ __launch_bounds__(256) void k_out(const float* __restrict__ Wo,
                                             const float* __restrict__ bo,
                                             float* __restrict__ out)
{
    int t = blockIdx.x * blockDim.x + threadIdx.x;
    int n = t >> 4, c = t & 15;
    if (n >= Nn) return;
    float acc = __ldg(bo + c);
    const float* hr = g_hid + n * 64;
    #pragma unroll
    for (int k = 0; k < 64; k++)
        acc = fmaf(hr[k], __ldg(Wo + k * 16 + c), acc);
    out[n * 16 + c] = acc;
}

// ---------------- launcher ----------------
extern "C" void kernel_launch(void* const* d_in, const int* in_sizes, int n_in,
                              void* d_out, int out_size)
{
    const float* x       = (const float*)d_in[0];
    const void*  ei      = d_in[1];
    const float* Wi      = (const float*)d_in[2];
    const float* bi      = (const float*)d_in[3];
    const float* Wq      = (const float*)d_in[4];
    const float* bq      = (const float*)d_in[5];
    const float* Wk      = (const float*)d_in[6];
    const float* bk      = (const float*)d_in[7];
    const float* Wv      = (const float*)d_in[8];
    const float* bv      = (const float*)d_in[9];
    const float* Wo      = (const float*)d_in[10];
    const float* bo      = (const float*)d_in[11];
    const float* hopwise = (const float*)d_in[12];
    const float* temp    = (const float*)d_in[13];
    float* out = (float*)d_out;

    k_zero_indeg<<<(Nn + 255) / 256, 256>>>();
    k_sniff<<<1, 32>>>((const int*)ei);
    k_edges<<<(Ee + 255) / 256, 256>>>(ei);
    k_scanA<<<NB, 256>>>();
    k_scanB<<<1, 256>>>();
    k_scanC<<<NB, 256>>>();
    k_scatter<<<(Ee + 255) / 256, 256>>>();
    k_sortrows<<<(Nn + 255) / 256, 256>>>();
    k_gamma<<<1, 32>>>(hopwise, temp);
    k_qkv<<<(Nn + 63) / 64, 256>>>(x, Wi, bi, Wq, bq, Wk, bk, Wv, bv);

    int hop_blocks = (Nn * Hh + 7) / 8;  // 8 warps/block, 1 warp per (head,node)
    k_hop1<<<hop_blocks, 256>>>();
    k_hop23<<<hop_blocks, 256>>>(2);
    k_hop23<<<hop_blocks, 256>>>(3);

    k_out<<<(Nn * 16 + 255) / 256, 256>>>(Wo, bo, out);
}